// round 1
// baseline (speedup 1.0000x reference)
#include <cuda_runtime.h>

#define N_NODES 8192
#define F_INDIM 512
#define H_DIM   256
#define D_DIM   64
#define N_EDGES 262144

// ---------------- scratch (device globals: no allocations allowed) ----------
__device__ float g_t1[N_NODES * H_DIM];   // x@W1+b1
__device__ float g_h [N_NODES * H_DIM];   // relu(spmm(t1))
__device__ float g_t2[N_NODES * D_DIM];   // h@W2+b2
__device__ int   g_cnt[N_NODES];
__device__ int   g_off[N_NODES + 1];
__device__ int   g_cur[N_NODES];
__device__ int   g_ccol[N_EDGES];
__device__ float g_cval[N_EDGES];

// ---------------- CSR build ------------------------------------------------
__global__ void k_zero_cnt() {
    int i = blockIdx.x * blockDim.x + threadIdx.x;
    if (i < N_NODES) g_cnt[i] = 0;
}

__global__ void k_hist(const int* __restrict__ rows) {
    int i = blockIdx.x * blockDim.x + threadIdx.x;
    if (i < N_EDGES) atomicAdd(&g_cnt[rows[i]], 1);
}

// 8192-wide exclusive scan, one block of 1024 threads, 8 items each.
__global__ void k_scan() {
    __shared__ int s[1024];
    int t = threadIdx.x;
    int loc[8];
    int sum = 0;
#pragma unroll
    for (int i = 0; i < 8; i++) { loc[i] = g_cnt[t * 8 + i]; sum += loc[i]; }
    s[t] = sum;
    __syncthreads();
    for (int off = 1; off < 1024; off <<= 1) {
        int v = (t >= off) ? s[t - off] : 0;
        __syncthreads();
        s[t] += v;
        __syncthreads();
    }
    int base = (t > 0) ? s[t - 1] : 0;
#pragma unroll
    for (int i = 0; i < 8; i++) {
        g_off[t * 8 + i] = base;
        g_cur[t * 8 + i] = base;
        base += loc[i];
    }
    if (t == 1023) g_off[N_NODES] = base;
}

__global__ void k_scatter(const int* __restrict__ rows, const int* __restrict__ cols,
                          const float* __restrict__ vals) {
    int i = blockIdx.x * blockDim.x + threadIdx.x;
    if (i < N_EDGES) {
        int r = rows[i];
        int p = atomicAdd(&g_cur[r], 1);
        g_ccol[p] = cols[i];
        g_cval[p] = vals[i];
    }
}

// ---------------- SpMM: one block per row, one thread per feature ----------
template <int F, int RELU>
__global__ void k_spmm(const float* __restrict__ src, float* __restrict__ dst) {
    __shared__ int   scol[F];
    __shared__ float sval[F];
    int r = blockIdx.x;
    int f = threadIdx.x;
    int s = g_off[r], e = g_off[r + 1];
    float acc = 0.0f;
    for (int base = s; base < e; base += F) {
        int n = e - base;
        if (n > F) n = F;
        if (f < n) { scol[f] = g_ccol[base + f]; sval[f] = g_cval[base + f]; }
        __syncthreads();
        for (int i = 0; i < n; i++)
            acc += sval[i] * src[scol[i] * F + f];
        __syncthreads();
    }
    dst[r * F + f] = RELU ? fmaxf(acc, 0.0f) : acc;
}

// ---------------- fp32 tiled GEMM with bias: C[M,Np] = A[M,K]@B[K,Np]+bias --
// 256 threads (16x16). Thread covers VM*4 rows x VN*4 cols, split-half float4
// pattern (m = vm*64 + ty*4, n = vn*64 + tx*4) for conflict-free LDS.128.
template <int BM, int BN, int BK>
__global__ __launch_bounds__(256) void k_gemm_bias(
    const float* __restrict__ A, const float* __restrict__ B,
    const float* __restrict__ bias, float* __restrict__ C,
    int M, int Np, int K) {
    constexpr int VM = BM / 64;
    constexpr int VN = BN / 64;
    __shared__ float sA[BK * BM];   // k-major: sA[k*BM+m]
    __shared__ float sB[BK * BN];   // k-major: sB[k*BN+n]
    int tid = threadIdx.x;
    int tx = tid & 15, ty = tid >> 4;
    int m0 = blockIdx.y * BM, n0 = blockIdx.x * BN;
    float acc[VM * 4][VN * 4];
#pragma unroll
    for (int i = 0; i < VM * 4; i++)
#pragma unroll
        for (int j = 0; j < VN * 4; j++) acc[i][j] = 0.0f;

    for (int k0 = 0; k0 < K; k0 += BK) {
        // A tile: BM x BK, transposed into k-major shared
        for (int i = tid; i < BM * BK / 4; i += 256) {
            int r = i / (BK / 4), q = i % (BK / 4);
            float4 v = *(const float4*)&A[(size_t)(m0 + r) * K + k0 + q * 4];
            sA[(q * 4 + 0) * BM + r] = v.x;
            sA[(q * 4 + 1) * BM + r] = v.y;
            sA[(q * 4 + 2) * BM + r] = v.z;
            sA[(q * 4 + 3) * BM + r] = v.w;
        }
        // B tile: BK x BN (already k-major)
        for (int i = tid; i < BK * BN / 4; i += 256) {
            int k = i / (BN / 4), q = i % (BN / 4);
            *(float4*)&sB[k * BN + q * 4] =
                *(const float4*)&B[(size_t)(k0 + k) * Np + n0 + q * 4];
        }
        __syncthreads();
#pragma unroll
        for (int k = 0; k < BK; k++) {
            float4 a[VM], b[VN];
#pragma unroll
            for (int vm = 0; vm < VM; vm++)
                a[vm] = *(float4*)&sA[k * BM + vm * 64 + ty * 4];
#pragma unroll
            for (int vn = 0; vn < VN; vn++)
                b[vn] = *(float4*)&sB[k * BN + vn * 64 + tx * 4];
#pragma unroll
            for (int vm = 0; vm < VM; vm++) {
                const float* ap = (const float*)&a[vm];
#pragma unroll
                for (int vn = 0; vn < VN; vn++) {
                    const float* bp = (const float*)&b[vn];
#pragma unroll
                    for (int i2 = 0; i2 < 4; i2++)
#pragma unroll
                        for (int j2 = 0; j2 < 4; j2++)
                            acc[vm * 4 + i2][vn * 4 + j2] += ap[i2] * bp[j2];
                }
            }
        }
        __syncthreads();
    }
#pragma unroll
    for (int vn = 0; vn < VN; vn++) {
        float4 bb = *(const float4*)&bias[n0 + vn * 64 + tx * 4];
#pragma unroll
        for (int vm = 0; vm < VM; vm++)
#pragma unroll
            for (int i2 = 0; i2 < 4; i2++) {
                int gm = m0 + vm * 64 + ty * 4 + i2;
                float4 o;
                o.x = acc[vm * 4 + i2][vn * 4 + 0] + bb.x;
                o.y = acc[vm * 4 + i2][vn * 4 + 1] + bb.y;
                o.z = acc[vm * 4 + i2][vn * 4 + 2] + bb.z;
                o.w = acc[vm * 4 + i2][vn * 4 + 3] + bb.w;
                *(float4*)&C[(size_t)gm * Np + n0 + vn * 64 + tx * 4] = o;
            }
    }
}

// ---------------- decode: rec = sigmoid(z @ z^T), z [8192,64] ---------------
// 128x128 tile per block, 256 threads, 8x8 per thread, K=64 fully resident.
__device__ __forceinline__ float sigmoidf_fast(float v) {
    return __fdividef(1.0f, 1.0f + __expf(-v));
}

__global__ __launch_bounds__(256) void k_zzt_sigmoid(const float* __restrict__ z,
                                                     float* __restrict__ rec) {
    extern __shared__ float sm[];
    float* sA = sm;             // [64][128] k-major
    float* sB = sm + 64 * 128;  // [64][128] k-major
    int tid = threadIdx.x;
    int tx = tid & 15, ty = tid >> 4;
    int m0 = blockIdx.y * 128, n0 = blockIdx.x * 128;
    const float4* Z4 = (const float4*)z;

    // load both tiles, transposing rows->k-major. STS conflict-free (r fastest).
    for (int i = tid; i < 128 * 16; i += 256) {
        int r = i & 127, q = i >> 7;   // q = which float4 of the 64-wide row
        float4 va = Z4[(m0 + r) * 16 + q];
        float4 vb = Z4[(n0 + r) * 16 + q];
        sA[(q * 4 + 0) * 128 + r] = va.x;
        sA[(q * 4 + 1) * 128 + r] = va.y;
        sA[(q * 4 + 2) * 128 + r] = va.z;
        sA[(q * 4 + 3) * 128 + r] = va.w;
        sB[(q * 4 + 0) * 128 + r] = vb.x;
        sB[(q * 4 + 1) * 128 + r] = vb.y;
        sB[(q * 4 + 2) * 128 + r] = vb.z;
        sB[(q * 4 + 3) * 128 + r] = vb.w;
    }
    __syncthreads();

    float acc[8][8];
#pragma unroll
    for (int i = 0; i < 8; i++)
#pragma unroll
        for (int j = 0; j < 8; j++) acc[i][j] = 0.0f;

#pragma unroll 8
    for (int k = 0; k < 64; k++) {
        float4 a0 = *(float4*)&sA[k * 128 + 0 * 64 + ty * 4];
        float4 a1 = *(float4*)&sA[k * 128 + 1 * 64 + ty * 4];
        float4 b0 = *(float4*)&sB[k * 128 + 0 * 64 + tx * 4];
        float4 b1 = *(float4*)&sB[k * 128 + 1 * 64 + tx * 4];
        float ra[8] = {a0.x, a0.y, a0.z, a0.w, a1.x, a1.y, a1.z, a1.w};
        float rb[8] = {b0.x, b0.y, b0.z, b0.w, b1.x, b1.y, b1.z, b1.w};
#pragma unroll
        for (int i = 0; i < 8; i++)
#pragma unroll
            for (int j = 0; j < 8; j++) acc[i][j] += ra[i] * rb[j];
    }

#pragma unroll
    for (int vm = 0; vm < 2; vm++)
#pragma unroll
        for (int i2 = 0; i2 < 4; i2++) {
            int gm = m0 + vm * 64 + ty * 4 + i2;
            int ai = vm * 4 + i2;
#pragma unroll
            for (int vn = 0; vn < 2; vn++) {
                float4 o;
                o.x = sigmoidf_fast(acc[ai][vn * 4 + 0]);
                o.y = sigmoidf_fast(acc[ai][vn * 4 + 1]);
                o.z = sigmoidf_fast(acc[ai][vn * 4 + 2]);
                o.w = sigmoidf_fast(acc[ai][vn * 4 + 3]);
                *(float4*)&rec[(size_t)gm * N_NODES + n0 + vn * 64 + tx * 4] = o;
            }
        }
}

// ---------------- launch ----------------------------------------------------
extern "C" void kernel_launch(void* const* d_in, const int* in_sizes, int n_in,
                              void* d_out, int out_size) {
    const float* x    = (const float*)d_in[0];
    const int*   rows = (const int*)d_in[1];
    const int*   cols = (const int*)d_in[2];
    const float* vals = (const float*)d_in[3];
    const float* W1   = (const float*)d_in[4];
    const float* b1   = (const float*)d_in[5];
    const float* W2   = (const float*)d_in[6];
    const float* b2   = (const float*)d_in[7];

    float* z   = (float*)d_out;                 // [8192, 64]
    float* rec = z + (size_t)N_NODES * D_DIM;   // [8192, 8192]

    void *pt1 = nullptr, *ph = nullptr, *pt2 = nullptr;
    cudaGetSymbolAddress(&pt1, g_t1);
    cudaGetSymbolAddress(&ph, g_h);
    cudaGetSymbolAddress(&pt2, g_t2);

    // CSR build (rebuilt every call; adjacency is an input)
    k_zero_cnt<<<N_NODES / 256, 256>>>();
    k_hist<<<N_EDGES / 256, 256>>>(rows);
    k_scan<<<1, 1024>>>();
    k_scatter<<<N_EDGES / 256, 256>>>(rows, cols, vals);

    // layer 1: t1 = x@W1+b1 ; h = relu(spmm(t1))
    k_gemm_bias<128, 128, 16><<<dim3(H_DIM / 128, N_NODES / 128), 256>>>(
        x, W1, b1, (float*)pt1, N_NODES, H_DIM, F_INDIM);
    k_spmm<H_DIM, 1><<<N_NODES, H_DIM>>>((const float*)pt1, (float*)ph);

    // layer 2: t2 = h@W2+b2 ; z = spmm(t2)
    k_gemm_bias<64, 64, 16><<<dim3(1, N_NODES / 64), 256>>>(
        (const float*)ph, W2, b2, (float*)pt2, N_NODES, D_DIM, H_DIM);
    k_spmm<D_DIM, 0><<<N_NODES, D_DIM>>>((const float*)pt2, z);

    // decode: rec = sigmoid(z z^T)
    cudaFuncSetAttribute(k_zzt_sigmoid, cudaFuncAttributeMaxDynamicSharedMemorySize,
                         64 * 128 * 2 * sizeof(float));
    k_zzt_sigmoid<<<dim3(N_NODES / 128, N_NODES / 128), 256,
                    64 * 128 * 2 * sizeof(float)>>>(z, rec);
}

// round 2
// speedup vs baseline: 1.0430x; 1.0430x over previous
#include <cuda_runtime.h>
#include <cstdint>

#define N_NODES 8192
#define F_INDIM 512
#define H_DIM   256
#define D_DIM   64
#define N_EDGES 262144

// ---------------- scratch (device globals: no allocations allowed) ----------
__device__ float g_t1[N_NODES * H_DIM];   // x@W1+b1
__device__ float g_h [N_NODES * H_DIM];   // relu(spmm(t1))
__device__ float g_t2[N_NODES * D_DIM];   // h@W2+b2
__device__ int   g_cnt[N_NODES];
__device__ int   g_off[N_NODES + 1];
__device__ int   g_cur[N_NODES];
__device__ int   g_ccol[N_EDGES];
__device__ float g_cval[N_EDGES];

// ---------------- CSR build ------------------------------------------------
__global__ void k_zero_cnt() {
    int i = blockIdx.x * blockDim.x + threadIdx.x;
    if (i < N_NODES) g_cnt[i] = 0;
}

__global__ void k_hist(const int* __restrict__ rows) {
    int i = blockIdx.x * blockDim.x + threadIdx.x;
    if (i < N_EDGES) atomicAdd(&g_cnt[rows[i]], 1);
}

__global__ void k_scan() {
    __shared__ int s[1024];
    int t = threadIdx.x;
    int loc[8];
    int sum = 0;
#pragma unroll
    for (int i = 0; i < 8; i++) { loc[i] = g_cnt[t * 8 + i]; sum += loc[i]; }
    s[t] = sum;
    __syncthreads();
    for (int off = 1; off < 1024; off <<= 1) {
        int v = (t >= off) ? s[t - off] : 0;
        __syncthreads();
        s[t] += v;
        __syncthreads();
    }
    int base = (t > 0) ? s[t - 1] : 0;
#pragma unroll
    for (int i = 0; i < 8; i++) {
        g_off[t * 8 + i] = base;
        g_cur[t * 8 + i] = base;
        base += loc[i];
    }
    if (t == 1023) g_off[N_NODES] = base;
}

__global__ void k_scatter(const int* __restrict__ rows, const int* __restrict__ cols,
                          const float* __restrict__ vals) {
    int i = blockIdx.x * blockDim.x + threadIdx.x;
    if (i < N_EDGES) {
        int r = rows[i];
        int p = atomicAdd(&g_cur[r], 1);
        g_ccol[p] = cols[i];
        g_cval[p] = vals[i];
    }
}

// ---------------- SpMM: one block per row, one thread per feature ----------
template <int F, int RELU>
__global__ void k_spmm(const float* __restrict__ src, float* __restrict__ dst) {
    __shared__ int   scol[F];
    __shared__ float sval[F];
    int r = blockIdx.x;
    int f = threadIdx.x;
    int s = g_off[r], e = g_off[r + 1];
    float acc = 0.0f;
    for (int base = s; base < e; base += F) {
        int n = e - base;
        if (n > F) n = F;
        if (f < n) { scol[f] = g_ccol[base + f]; sval[f] = g_cval[base + f]; }
        __syncthreads();
        for (int i = 0; i < n; i++)
            acc += sval[i] * src[scol[i] * F + f];
        __syncthreads();
    }
    dst[r * F + f] = RELU ? fmaxf(acc, 0.0f) : acc;
}

// ---------------- tf32 tensor-core machinery --------------------------------
__device__ __forceinline__ uint32_t cvt_tf32(float f) {
    uint32_t r;
    asm("cvt.rna.tf32.f32 %0, %1;" : "=r"(r) : "f"(f));
    return r;
}

__device__ __forceinline__ void split_tf32(float a, float& hi, float& lo) {
    uint32_t h = cvt_tf32(a);
    float hf = __uint_as_float(h);
    hi = hf;
    lo = __uint_as_float(cvt_tf32(a - hf));
}

__device__ __forceinline__ void mma8(float* c, const uint32_t* a, const uint32_t* b) {
    asm volatile(
        "mma.sync.aligned.m16n8k8.row.col.f32.tf32.tf32.f32 "
        "{%0,%1,%2,%3}, {%4,%5,%6,%7}, {%8,%9}, {%0,%1,%2,%3};"
        : "+f"(c[0]), "+f"(c[1]), "+f"(c[2]), "+f"(c[3])
        : "r"(a[0]), "r"(a[1]), "r"(a[2]), "r"(a[3]), "r"(b[0]), "r"(b[1]));
}

// ---------------- tf32x2 GEMM with bias: C[M,N] = A[M,K]@B[K,N]+bias --------
// 256 threads. A split hi/lo in smem as [m][k] (stride BK+1); B as [k][n]
// (stride BN+1). Error ~2^-21 (near-fp32).
template <int BM, int BN, int BK, int WM, int WN>
__global__ __launch_bounds__(256) void k_gemm_tf32x2(
    const float* __restrict__ A, const float* __restrict__ B,
    const float* __restrict__ bias, float* __restrict__ C,
    int M, int N, int K) {
    constexpr int SASTR = BK + 1;
    constexpr int SBSTR = BN + 1;
    constexpr int WNC = BN / WN;
    constexpr int MT = WM / 16;
    constexpr int NT = WN / 8;
    extern __shared__ float sm[];
    float* sAh = sm;
    float* sAl = sAh + BM * SASTR;
    float* sBh = sAl + BM * SASTR;
    float* sBl = sBh + BK * SBSTR;

    int tid = threadIdx.x, wid = tid >> 5, lane = tid & 31;
    int gid = lane >> 2, tig = lane & 3;
    int wm = (wid / WNC) * WM, wn = (wid % WNC) * WN;
    int m0 = blockIdx.y * BM, n0 = blockIdx.x * BN;

    float acc[MT][NT][4];
#pragma unroll
    for (int i = 0; i < MT; i++)
#pragma unroll
        for (int j = 0; j < NT; j++)
#pragma unroll
            for (int q = 0; q < 4; q++) acc[i][j][q] = 0.0f;

    for (int k0 = 0; k0 < K; k0 += BK) {
        // A tile: BM x BK
        for (int i = tid; i < BM * BK / 4; i += 256) {
            int r = i / (BK / 4), q = i % (BK / 4);
            float4 v = *(const float4*)&A[(size_t)(m0 + r) * K + k0 + q * 4];
            float vv[4] = {v.x, v.y, v.z, v.w};
            int base = r * SASTR + q * 4;
#pragma unroll
            for (int j = 0; j < 4; j++) {
                float hi, lo;
                split_tf32(vv[j], hi, lo);
                sAh[base + j] = hi;
                sAl[base + j] = lo;
            }
        }
        // B tile: BK x BN
        for (int i = tid; i < BK * BN / 4; i += 256) {
            int r = i / (BN / 4), q = i % (BN / 4);
            float4 v = *(const float4*)&B[(size_t)(k0 + r) * N + n0 + q * 4];
            float vv[4] = {v.x, v.y, v.z, v.w};
            int base = r * SBSTR + q * 4;
#pragma unroll
            for (int j = 0; j < 4; j++) {
                float hi, lo;
                split_tf32(vv[j], hi, lo);
                sBh[base + j] = hi;
                sBl[base + j] = lo;
            }
        }
        __syncthreads();
#pragma unroll
        for (int kc = 0; kc < BK; kc += 8) {
            uint32_t ah[MT][4], al[MT][4];
#pragma unroll
            for (int mt = 0; mt < MT; mt++) {
                int r0 = wm + mt * 16 + gid;
                ah[mt][0] = __float_as_uint(sAh[r0 * SASTR + kc + tig]);
                ah[mt][1] = __float_as_uint(sAh[(r0 + 8) * SASTR + kc + tig]);
                ah[mt][2] = __float_as_uint(sAh[r0 * SASTR + kc + tig + 4]);
                ah[mt][3] = __float_as_uint(sAh[(r0 + 8) * SASTR + kc + tig + 4]);
                al[mt][0] = __float_as_uint(sAl[r0 * SASTR + kc + tig]);
                al[mt][1] = __float_as_uint(sAl[(r0 + 8) * SASTR + kc + tig]);
                al[mt][2] = __float_as_uint(sAl[r0 * SASTR + kc + tig + 4]);
                al[mt][3] = __float_as_uint(sAl[(r0 + 8) * SASTR + kc + tig + 4]);
            }
            uint32_t bh[NT][2], bl[NT][2];
#pragma unroll
            for (int nt = 0; nt < NT; nt++) {
                int c0 = wn + nt * 8 + gid;
                bh[nt][0] = __float_as_uint(sBh[(kc + tig) * SBSTR + c0]);
                bh[nt][1] = __float_as_uint(sBh[(kc + tig + 4) * SBSTR + c0]);
                bl[nt][0] = __float_as_uint(sBl[(kc + tig) * SBSTR + c0]);
                bl[nt][1] = __float_as_uint(sBl[(kc + tig + 4) * SBSTR + c0]);
            }
#pragma unroll
            for (int mt = 0; mt < MT; mt++)
#pragma unroll
                for (int nt = 0; nt < NT; nt++) {
                    mma8(acc[mt][nt], ah[mt], bh[nt]);
                    mma8(acc[mt][nt], ah[mt], bl[nt]);
                    mma8(acc[mt][nt], al[mt], bh[nt]);
                }
        }
        __syncthreads();
    }
    // epilogue: bias + store
#pragma unroll
    for (int mt = 0; mt < MT; mt++) {
        int row0 = m0 + wm + mt * 16 + gid;
#pragma unroll
        for (int nt = 0; nt < NT; nt++) {
            int col = n0 + wn + nt * 8 + 2 * tig;
            float bx = bias[col], by = bias[col + 1];
            float2 o0 = {acc[mt][nt][0] + bx, acc[mt][nt][1] + by};
            float2 o1 = {acc[mt][nt][2] + bx, acc[mt][nt][3] + by};
            *(float2*)&C[(size_t)row0 * N + col] = o0;
            *(float2*)&C[(size_t)(row0 + 8) * N + col] = o1;
        }
    }
}

// ---------------- decode: rec = sigmoid(z @ z^T), z [8192,64], tf32 ---------
__device__ __forceinline__ float sigmoidf_fast(float v) {
    return __fdividef(1.0f, 1.0f + __expf(-v));
}

__global__ __launch_bounds__(256) void k_zzt_tf32(const float* __restrict__ z,
                                                  float* __restrict__ rec) {
    constexpr int SSTR = 65;  // 64 k + 1 pad
    extern __shared__ float sm[];
    float* sA = sm;               // [128][65]  z rows (m)
    float* sB = sm + 128 * SSTR;  // [128][65]  z rows (n)
    int tid = threadIdx.x, wid = tid >> 5, lane = tid & 31;
    int gid = lane >> 2, tig = lane & 3;
    int wm = (wid >> 2) * 64, wn = (wid & 3) * 32;  // warp tile 64x32
    int m0 = blockIdx.y * 128, n0 = blockIdx.x * 128;
    const float4* Z4 = (const float4*)z;

    // load tiles, round to tf32 once at store
    for (int i = tid; i < 128 * 16; i += 256) {
        int r = i >> 4, q = i & 15;
        float4 va = Z4[(m0 + r) * 16 + q];
        float4 vb = Z4[(n0 + r) * 16 + q];
        int base = r * SSTR + q * 4;
        sA[base + 0] = __uint_as_float(cvt_tf32(va.x));
        sA[base + 1] = __uint_as_float(cvt_tf32(va.y));
        sA[base + 2] = __uint_as_float(cvt_tf32(va.z));
        sA[base + 3] = __uint_as_float(cvt_tf32(va.w));
        sB[base + 0] = __uint_as_float(cvt_tf32(vb.x));
        sB[base + 1] = __uint_as_float(cvt_tf32(vb.y));
        sB[base + 2] = __uint_as_float(cvt_tf32(vb.z));
        sB[base + 3] = __uint_as_float(cvt_tf32(vb.w));
    }
    __syncthreads();

    float acc[4][4][4];
#pragma unroll
    for (int i = 0; i < 4; i++)
#pragma unroll
        for (int j = 0; j < 4; j++)
#pragma unroll
            for (int q = 0; q < 4; q++) acc[i][j][q] = 0.0f;

#pragma unroll
    for (int kc = 0; kc < 64; kc += 8) {
        uint32_t af[4][4];
#pragma unroll
        for (int mt = 0; mt < 4; mt++) {
            int r0 = wm + mt * 16 + gid;
            af[mt][0] = __float_as_uint(sA[r0 * SSTR + kc + tig]);
            af[mt][1] = __float_as_uint(sA[(r0 + 8) * SSTR + kc + tig]);
            af[mt][2] = __float_as_uint(sA[r0 * SSTR + kc + tig + 4]);
            af[mt][3] = __float_as_uint(sA[(r0 + 8) * SSTR + kc + tig + 4]);
        }
        uint32_t bf[4][2];
#pragma unroll
        for (int nt = 0; nt < 4; nt++) {
            int c0 = wn + nt * 8 + gid;
            bf[nt][0] = __float_as_uint(sB[c0 * SSTR + kc + tig]);
            bf[nt][1] = __float_as_uint(sB[c0 * SSTR + kc + tig + 4]);
        }
#pragma unroll
        for (int mt = 0; mt < 4; mt++)
#pragma unroll
            for (int nt = 0; nt < 4; nt++) mma8(acc[mt][nt], af[mt], bf[nt]);
    }

#pragma unroll
    for (int mt = 0; mt < 4; mt++) {
        int row = m0 + wm + mt * 16 + gid;
#pragma unroll
        for (int nt = 0; nt < 4; nt++) {
            int col = n0 + wn + nt * 8 + 2 * tig;
            float2 o0 = {sigmoidf_fast(acc[mt][nt][0]), sigmoidf_fast(acc[mt][nt][1])};
            float2 o1 = {sigmoidf_fast(acc[mt][nt][2]), sigmoidf_fast(acc[mt][nt][3])};
            *(float2*)&rec[(size_t)row * N_NODES + col] = o0;
            *(float2*)&rec[(size_t)(row + 8) * N_NODES + col] = o1;
        }
    }
}

// ---------------- launch ----------------------------------------------------
extern "C" void kernel_launch(void* const* d_in, const int* in_sizes, int n_in,
                              void* d_out, int out_size) {
    const float* x    = (const float*)d_in[0];
    const int*   rows = (const int*)d_in[1];
    const int*   cols = (const int*)d_in[2];
    const float* vals = (const float*)d_in[3];
    const float* W1   = (const float*)d_in[4];
    const float* b1   = (const float*)d_in[5];
    const float* W2   = (const float*)d_in[6];
    const float* b2   = (const float*)d_in[7];

    float* z   = (float*)d_out;                 // [8192, 64]
    float* rec = z + (size_t)N_NODES * D_DIM;   // [8192, 8192]

    void *pt1 = nullptr, *ph = nullptr, *pt2 = nullptr;
    cudaGetSymbolAddress(&pt1, g_t1);
    cudaGetSymbolAddress(&ph, g_h);
    cudaGetSymbolAddress(&pt2, g_t2);

    // CSR build
    k_zero_cnt<<<N_NODES / 256, 256>>>();
    k_hist<<<N_EDGES / 256, 256>>>(rows);
    k_scan<<<1, 1024>>>();
    k_scatter<<<N_EDGES / 256, 256>>>(rows, cols, vals);

    // layer 1: t1 = x@W1+b1 (tf32x2) ; h = relu(spmm(t1))
    {
        constexpr int BM = 128, BN = 128, BK = 32;
        size_t smem = (size_t)(BM * (BK + 1) * 2 + BK * (BN + 1) * 2) * sizeof(float);
        cudaFuncSetAttribute(k_gemm_tf32x2<BM, BN, BK, 64, 32>,
                             cudaFuncAttributeMaxDynamicSharedMemorySize, (int)smem);
        k_gemm_tf32x2<BM, BN, BK, 64, 32>
            <<<dim3(H_DIM / BN, N_NODES / BM), 256, smem>>>(
                x, W1, b1, (float*)pt1, N_NODES, H_DIM, F_INDIM);
    }
    k_spmm<H_DIM, 1><<<N_NODES, H_DIM>>>((const float*)pt1, (float*)ph);

    // layer 2: t2 = h@W2+b2 (tf32x2) ; z = spmm(t2)
    {
        constexpr int BM = 64, BN = 64, BK = 32;
        size_t smem = (size_t)(BM * (BK + 1) * 2 + BK * (BN + 1) * 2) * sizeof(float);
        cudaFuncSetAttribute(k_gemm_tf32x2<BM, BN, BK, 32, 16>,
                             cudaFuncAttributeMaxDynamicSharedMemorySize, (int)smem);
        k_gemm_tf32x2<BM, BN, BK, 32, 16>
            <<<dim3(D_DIM / BN, N_NODES / BM), 256, smem>>>(
                (const float*)ph, W2, b2, (float*)pt2, N_NODES, D_DIM, H_DIM);
    }
    k_spmm<D_DIM, 0><<<N_NODES, D_DIM>>>((const float*)pt2, z);

    // decode: rec = sigmoid(z z^T), single-pass tf32
    {
        size_t smem = (size_t)(2 * 128 * 65) * sizeof(float);
        cudaFuncSetAttribute(k_zzt_tf32,
                             cudaFuncAttributeMaxDynamicSharedMemorySize, (int)smem);
        k_zzt_tf32<<<dim3(N_NODES / 128, N_NODES / 128), 256, smem>>>(z, rec);
    }
}

// round 6
// speedup vs baseline: 1.2186x; 1.1684x over previous
#include <cuda_runtime.h>
#include <cstdint>

#define N_NODES 8192
#define F_INDIM 512
#define H_DIM   256
#define D_DIM   64
#define N_EDGES 262144

// ---------------- scratch (device globals: no allocations allowed) ----------
__device__ float g_t1[N_NODES * H_DIM];
__device__ float g_h [N_NODES * H_DIM];
__device__ float g_t2[N_NODES * D_DIM];
__device__ int   g_cnt[N_NODES];
__device__ int   g_off[N_NODES + 1];
__device__ int   g_cur[N_NODES];
__device__ int   g_ccol[N_EDGES];
__device__ float g_cval[N_EDGES];

// ---------------- tf32 machinery (mma.sync only — tcgen05 is rejected by the
// harness's compute_103 virtual-arch PTX pass) ------------------------------
__device__ __forceinline__ uint32_t cvt_tf32(float f) {
    uint32_t r;
    asm("cvt.rna.tf32.f32 %0, %1;" : "=r"(r) : "f"(f));
    return r;
}
__device__ __forceinline__ void split_tf32(float a, float& hi, float& lo) {
    float hf = __uint_as_float(cvt_tf32(a));
    hi = hf;
    lo = __uint_as_float(cvt_tf32(a - hf));
}
__device__ __forceinline__ void mma8(float* c, const uint32_t* a, const uint32_t* b) {
    asm volatile(
        "mma.sync.aligned.m16n8k8.row.col.f32.tf32.tf32.f32 "
        "{%0,%1,%2,%3}, {%4,%5,%6,%7}, {%8,%9}, {%0,%1,%2,%3};"
        : "+f"(c[0]), "+f"(c[1]), "+f"(c[2]), "+f"(c[3])
        : "r"(a[0]), "r"(a[1]), "r"(a[2]), "r"(a[3]), "r"(b[0]), "r"(b[1]));
}

// ---------------- CSR build ------------------------------------------------
__global__ void k_hist(const int* __restrict__ rows) {
    int i = blockIdx.x * blockDim.x + threadIdx.x;
    if (i < N_EDGES) atomicAdd(&g_cnt[rows[i]], 1);
}
// scan also RESETS g_cnt to zero for the next call (g_cnt starts zeroed at
// module load; k_hist accumulates; we consume + clear here).
__global__ void k_scan() {
    __shared__ int s[1024];
    int t = threadIdx.x;
    int loc[8];
    int sum = 0;
#pragma unroll
    for (int i = 0; i < 8; i++) {
        loc[i] = g_cnt[t * 8 + i];
        g_cnt[t * 8 + i] = 0;
        sum += loc[i];
    }
    s[t] = sum;
    __syncthreads();
    for (int off = 1; off < 1024; off <<= 1) {
        int v = (t >= off) ? s[t - off] : 0;
        __syncthreads();
        s[t] += v;
        __syncthreads();
    }
    int base = (t > 0) ? s[t - 1] : 0;
#pragma unroll
    for (int i = 0; i < 8; i++) {
        g_off[t * 8 + i] = base;
        g_cur[t * 8 + i] = base;
        base += loc[i];
    }
    if (t == 1023) g_off[N_NODES] = base;
}
__global__ void k_scatter(const int* __restrict__ rows, const int* __restrict__ cols,
                          const float* __restrict__ vals) {
    int i = blockIdx.x * blockDim.x + threadIdx.x;
    if (i < N_EDGES) {
        int r = rows[i];
        int p = atomicAdd(&g_cur[r], 1);
        g_ccol[p] = cols[i];
        g_cval[p] = vals[i];
    }
}

// ---------------- SpMM -----------------------------------------------------
template <int F, int RELU>
__global__ void k_spmm(const float* __restrict__ src, float* __restrict__ dst) {
    __shared__ int   scol[F];
    __shared__ float sval[F];
    int r = blockIdx.x;
    int f = threadIdx.x;
    int s = g_off[r], e = g_off[r + 1];
    float acc = 0.0f;
    for (int base = s; base < e; base += F) {
        int n = e - base;
        if (n > F) n = F;
        if (f < n) { scol[f] = g_ccol[base + f]; sval[f] = g_cval[base + f]; }
        __syncthreads();
        for (int i = 0; i < n; i++)
            acc += sval[i] * src[scol[i] * F + f];
        __syncthreads();
    }
    dst[r * F + f] = RELU ? fmaxf(acc, 0.0f) : acc;
}

// ---------------- tf32x2 mma.sync GEMM (layers 1/2, near-fp32) --------------
template <int BM, int BN, int BK, int WM, int WN>
__global__ __launch_bounds__(256) void k_gemm_tf32x2(
    const float* __restrict__ A, const float* __restrict__ B,
    const float* __restrict__ bias, float* __restrict__ C,
    int M, int N, int K) {
    constexpr int SASTR = BK + 1;
    constexpr int SBSTR = BN + 1;
    constexpr int WNC = BN / WN;
    constexpr int MT = WM / 16;
    constexpr int NT = WN / 8;
    extern __shared__ float sm[];
    float* sAh = sm;
    float* sAl = sAh + BM * SASTR;
    float* sBh = sAl + BM * SASTR;
    float* sBl = sBh + BK * SBSTR;

    int tid = threadIdx.x, wid = tid >> 5, lane = tid & 31;
    int gid = lane >> 2, tig = lane & 3;
    int wm = (wid / WNC) * WM, wn = (wid % WNC) * WN;
    int m0 = blockIdx.y * BM, n0 = blockIdx.x * BN;

    float acc[MT][NT][4];
#pragma unroll
    for (int i = 0; i < MT; i++)
#pragma unroll
        for (int j = 0; j < NT; j++)
#pragma unroll
            for (int q = 0; q < 4; q++) acc[i][j][q] = 0.0f;

    for (int k0 = 0; k0 < K; k0 += BK) {
        for (int i = tid; i < BM * BK / 4; i += 256) {
            int r = i / (BK / 4), q = i % (BK / 4);
            float4 v = *(const float4*)&A[(size_t)(m0 + r) * K + k0 + q * 4];
            float vv[4] = {v.x, v.y, v.z, v.w};
            int base = r * SASTR + q * 4;
#pragma unroll
            for (int j = 0; j < 4; j++) {
                float hi, lo;
                split_tf32(vv[j], hi, lo);
                sAh[base + j] = hi;
                sAl[base + j] = lo;
            }
        }
        for (int i = tid; i < BK * BN / 4; i += 256) {
            int r = i / (BN / 4), q = i % (BN / 4);
            float4 v = *(const float4*)&B[(size_t)(k0 + r) * N + n0 + q * 4];
            float vv[4] = {v.x, v.y, v.z, v.w};
            int base = r * SBSTR + q * 4;
#pragma unroll
            for (int j = 0; j < 4; j++) {
                float hi, lo;
                split_tf32(vv[j], hi, lo);
                sBh[base + j] = hi;
                sBl[base + j] = lo;
            }
        }
        __syncthreads();
#pragma unroll
        for (int kc = 0; kc < BK; kc += 8) {
            uint32_t ah[MT][4], al[MT][4];
#pragma unroll
            for (int mt = 0; mt < MT; mt++) {
                int r0 = wm + mt * 16 + gid;
                ah[mt][0] = __float_as_uint(sAh[r0 * SASTR + kc + tig]);
                ah[mt][1] = __float_as_uint(sAh[(r0 + 8) * SASTR + kc + tig]);
                ah[mt][2] = __float_as_uint(sAh[r0 * SASTR + kc + tig + 4]);
                ah[mt][3] = __float_as_uint(sAh[(r0 + 8) * SASTR + kc + tig + 4]);
                al[mt][0] = __float_as_uint(sAl[r0 * SASTR + kc + tig]);
                al[mt][1] = __float_as_uint(sAl[(r0 + 8) * SASTR + kc + tig]);
                al[mt][2] = __float_as_uint(sAl[r0 * SASTR + kc + tig + 4]);
                al[mt][3] = __float_as_uint(sAl[(r0 + 8) * SASTR + kc + tig + 4]);
            }
            uint32_t bh[NT][2], bl[NT][2];
#pragma unroll
            for (int nt = 0; nt < NT; nt++) {
                int c0 = wn + nt * 8 + gid;
                bh[nt][0] = __float_as_uint(sBh[(kc + tig) * SBSTR + c0]);
                bh[nt][1] = __float_as_uint(sBh[(kc + tig + 4) * SBSTR + c0]);
                bl[nt][0] = __float_as_uint(sBl[(kc + tig) * SBSTR + c0]);
                bl[nt][1] = __float_as_uint(sBl[(kc + tig + 4) * SBSTR + c0]);
            }
#pragma unroll
            for (int mt = 0; mt < MT; mt++)
#pragma unroll
                for (int nt = 0; nt < NT; nt++) {
                    mma8(acc[mt][nt], ah[mt], bh[nt]);
                    mma8(acc[mt][nt], ah[mt], bl[nt]);
                    mma8(acc[mt][nt], al[mt], bh[nt]);
                }
        }
        __syncthreads();
    }
#pragma unroll
    for (int mt = 0; mt < MT; mt++) {
        int row0 = m0 + wm + mt * 16 + gid;
#pragma unroll
        for (int nt = 0; nt < NT; nt++) {
            int col = n0 + wn + nt * 8 + 2 * tig;
            float bx = bias[col], by = bias[col + 1];
            float2 o0 = {acc[mt][nt][0] + bx, acc[mt][nt][1] + by};
            float2 o1 = {acc[mt][nt][2] + bx, acc[mt][nt][3] + by};
            *(float2*)&C[(size_t)row0 * N + col] = o0;
            *(float2*)&C[(size_t)(row0 + 8) * N + col] = o1;
        }
    }
}

// ---------------- decode: rec = sigmoid(z z^T), symmetric tf32 mma ----------
// Only upper-triangular 128x128 tiles are computed (2080 of 4096); off-diagonal
// tiles are mirrored through a padded smem transpose buffer so both stores
// stay coalesced.
__device__ __forceinline__ float sigmoidf_fast(float v) {
    return __fdividef(1.0f, 1.0f + __expf(-v));
}

#define ZSTR 65    // k-stride padding for z tiles
#define TSTR 132   // transpose buffer stride (16B aligned, conflict-free STS)
#define ZZT_SMEM (128 * TSTR * 4)   // 67584 >= 2*128*65*4 = 66560

__global__ __launch_bounds__(256) void k_zzt_sym(const float* __restrict__ z,
                                                 float* __restrict__ rec) {
    extern __shared__ float sm[];
    float* sA = sm;                // [128][65] rows m0..
    float* sB = sm + 128 * ZSTR;   // [128][65] rows n0..
    float* sT = sm;                // reused after compute: [128][132] transpose

    int tid = threadIdx.x, wid = tid >> 5, lane = tid & 31;
    int gid = lane >> 2, tig = lane & 3;
    int wm = (wid >> 2) * 64, wn = (wid & 3) * 32;

    // decode upper-triangular pair (bi <= bj) from linear block id
    int k = blockIdx.x, bi = 0, rem = 64;
    while (k >= rem) { k -= rem; rem--; bi++; }
    int bj = bi + k;
    int m0 = bi * 128, n0 = bj * 128;

    const float4* Z4 = (const float4*)z;
    for (int i = tid; i < 128 * 16; i += 256) {
        int r = i >> 4, q = i & 15;
        float4 va = Z4[(size_t)(m0 + r) * 16 + q];
        float4 vb = Z4[(size_t)(n0 + r) * 16 + q];
        int base = r * ZSTR + q * 4;
        sA[base + 0] = __uint_as_float(cvt_tf32(va.x));
        sA[base + 1] = __uint_as_float(cvt_tf32(va.y));
        sA[base + 2] = __uint_as_float(cvt_tf32(va.z));
        sA[base + 3] = __uint_as_float(cvt_tf32(va.w));
        sB[base + 0] = __uint_as_float(cvt_tf32(vb.x));
        sB[base + 1] = __uint_as_float(cvt_tf32(vb.y));
        sB[base + 2] = __uint_as_float(cvt_tf32(vb.z));
        sB[base + 3] = __uint_as_float(cvt_tf32(vb.w));
    }
    __syncthreads();

    float acc[4][4][4];
#pragma unroll
    for (int i = 0; i < 4; i++)
#pragma unroll
        for (int j = 0; j < 4; j++)
#pragma unroll
            for (int q = 0; q < 4; q++) acc[i][j][q] = 0.0f;

#pragma unroll
    for (int kc = 0; kc < 64; kc += 8) {
        uint32_t af[4][4];
#pragma unroll
        for (int mt = 0; mt < 4; mt++) {
            int r0 = wm + mt * 16 + gid;
            af[mt][0] = __float_as_uint(sA[r0 * ZSTR + kc + tig]);
            af[mt][1] = __float_as_uint(sA[(r0 + 8) * ZSTR + kc + tig]);
            af[mt][2] = __float_as_uint(sA[r0 * ZSTR + kc + tig + 4]);
            af[mt][3] = __float_as_uint(sA[(r0 + 8) * ZSTR + kc + tig + 4]);
        }
        uint32_t bf[4][2];
#pragma unroll
        for (int nt = 0; nt < 4; nt++) {
            int c0 = wn + nt * 8 + gid;
            bf[nt][0] = __float_as_uint(sB[c0 * ZSTR + kc + tig]);
            bf[nt][1] = __float_as_uint(sB[c0 * ZSTR + kc + tig + 4]);
        }
#pragma unroll
        for (int mt = 0; mt < 4; mt++)
#pragma unroll
            for (int nt = 0; nt < 4; nt++) mma8(acc[mt][nt], af[mt], bf[nt]);
    }

    // sigmoid in place
#pragma unroll
    for (int i = 0; i < 4; i++)
#pragma unroll
        for (int j = 0; j < 4; j++)
#pragma unroll
            for (int q = 0; q < 4; q++) acc[i][j][q] = sigmoidf_fast(acc[i][j][q]);

    // direct tile store (m0, n0)
#pragma unroll
    for (int mt = 0; mt < 4; mt++) {
        int row = m0 + wm + mt * 16 + gid;
#pragma unroll
        for (int nt = 0; nt < 4; nt++) {
            int col = n0 + wn + nt * 8 + 2 * tig;
            float2 o0 = {acc[mt][nt][0], acc[mt][nt][1]};
            float2 o1 = {acc[mt][nt][2], acc[mt][nt][3]};
            *(float2*)&rec[(size_t)row * N_NODES + col] = o0;
            *(float2*)&rec[(size_t)(row + 8) * N_NODES + col] = o1;
        }
    }

    if (bi == bj) return;

    // mirror store (n0, m0): transpose through smem.
    __syncthreads();  // everyone done reading sA/sB
    // sT[c][r] = tile[r][c]; STS banks: (4c + r) % 32 -> (8*tig + gid) distinct
#pragma unroll
    for (int mt = 0; mt < 4; mt++) {
        int r = wm + mt * 16 + gid;
#pragma unroll
        for (int nt = 0; nt < 4; nt++) {
            int c = wn + nt * 8 + 2 * tig;
            sT[(c + 0) * TSTR + r]     = acc[mt][nt][0];
            sT[(c + 1) * TSTR + r]     = acc[mt][nt][1];
            sT[(c + 0) * TSTR + r + 8] = acc[mt][nt][2];
            sT[(c + 1) * TSTR + r + 8] = acc[mt][nt][3];
        }
    }
    __syncthreads();
    // write transposed tile: row c of mirror = sT[c][0..127], contiguous float4
#pragma unroll
    for (int it = 0; it < 16; it++) {
        int i = tid + it * 256;          // 4096 float4 total
        int c = i >> 5, r4 = i & 31;     // one warp per output row chunk
        float4 v = *(float4*)&sT[c * TSTR + r4 * 4];
        *(float4*)&rec[(size_t)(n0 + c) * N_NODES + m0 + r4 * 4] = v;
    }
}

// ---------------- launch ----------------------------------------------------
extern "C" void kernel_launch(void* const* d_in, const int* in_sizes, int n_in,
                              void* d_out, int out_size) {
    const float* x    = (const float*)d_in[0];
    const int*   rows = (const int*)d_in[1];
    const int*   cols = (const int*)d_in[2];
    const float* vals = (const float*)d_in[3];
    const float* W1   = (const float*)d_in[4];
    const float* b1   = (const float*)d_in[5];
    const float* W2   = (const float*)d_in[6];
    const float* b2   = (const float*)d_in[7];

    float* z   = (float*)d_out;
    float* rec = z + (size_t)N_NODES * D_DIM;

    void *pt1 = nullptr, *ph = nullptr, *pt2 = nullptr;
    cudaGetSymbolAddress(&pt1, g_t1);
    cudaGetSymbolAddress(&ph, g_h);
    cudaGetSymbolAddress(&pt2, g_t2);

    // CSR build (g_cnt cleared by previous call's k_scan; zero at module load)
    k_hist<<<N_EDGES / 256, 256>>>(rows);
    k_scan<<<1, 1024>>>();
    k_scatter<<<N_EDGES / 256, 256>>>(rows, cols, vals);

    // layer 1
    {
        constexpr int BM = 128, BN = 128, BK = 32;
        size_t smem = (size_t)(BM * (BK + 1) * 2 + BK * (BN + 1) * 2) * sizeof(float);
        cudaFuncSetAttribute(k_gemm_tf32x2<BM, BN, BK, 64, 32>,
                             cudaFuncAttributeMaxDynamicSharedMemorySize, (int)smem);
        k_gemm_tf32x2<BM, BN, BK, 64, 32>
            <<<dim3(H_DIM / BN, N_NODES / BM), 256, smem>>>(
                x, W1, b1, (float*)pt1, N_NODES, H_DIM, F_INDIM);
    }
    k_spmm<H_DIM, 1><<<N_NODES, H_DIM>>>((const float*)pt1, (float*)ph);

    // layer 2
    {
        constexpr int BM = 64, BN = 64, BK = 32;
        size_t smem = (size_t)(BM * (BK + 1) * 2 + BK * (BN + 1) * 2) * sizeof(float);
        cudaFuncSetAttribute(k_gemm_tf32x2<BM, BN, BK, 32, 16>,
                             cudaFuncAttributeMaxDynamicSharedMemorySize, (int)smem);
        k_gemm_tf32x2<BM, BN, BK, 32, 16>
            <<<dim3(D_DIM / BN, N_NODES / BM), 256, smem>>>(
                (const float*)ph, W2, b2, (float*)pt2, N_NODES, D_DIM, H_DIM);
    }
    k_spmm<D_DIM, 0><<<N_NODES, D_DIM>>>((const float*)pt2, z);

    // decode: symmetric upper-triangular tiles (2080 blocks)
    cudaFuncSetAttribute(k_zzt_sym, cudaFuncAttributeMaxDynamicSharedMemorySize, ZZT_SMEM);
    k_zzt_sym<<<64 * 65 / 2, 256, ZZT_SMEM>>>(z, rec);
}